// round 2
// baseline (speedup 1.0000x reference)
#include <cuda_runtime.h>
#include <math.h>

#define BB 8
#define LC 512
#define LQ 64
#define DD 256
#define TI 32
#define NEG_BIG 1e30f

// scratch between kernels (device globals: allocation-free)
__device__ float g_ctx1[BB * LC];
__device__ float g_U[BB * LC];
__device__ float g_m[BB * LC];

__global__ __launch_bounds__(128) void bi_attn_main(
    const float* __restrict__ ctx, const float* __restrict__ qst,
    const int* __restrict__ mask, const float* __restrict__ att_w,
    const float* __restrict__ att_b, const float* __restrict__ w_in,
    const float* __restrict__ w_mem)
{
    __shared__ float sC[TI][68];       // context rows premultiplied by w_p
    __shared__ float sQ[LQ][68];       // raw question rows
    __shared__ float s_sc[TI], s_c1[TI], s_sq[LQ], s_q1[LQ], s_pen[LQ];

    const int b   = blockIdx.y;
    const int i0  = blockIdx.x * TI;
    const int tid = threadIdx.x;

    const float* wc = att_w;            // [0,D)
    const float* wq = att_w + DD;       // [D,2D)
    const float* wp = att_w + 2 * DD;   // [2D,3D)

    if (tid < LQ) {
        float mf = (float)mask[b * LQ + tid];
        s_pen[tid] = -NEG_BIG * (1.0f - mf);
    }

    // load-thread mapping (constant across chunks)
    const int cr  = tid >> 2;   // ctx row 0..31, 4 threads per row
    const int cf0 = tid & 3;
    const int qr  = tid >> 1;   // q row 0..63, 2 threads per row
    const int qf0 = tid & 1;

    // GEMM thread mapping: 8 ti-groups x 16 tj-groups, 4x4 tile each
    const int ti_ = tid >> 4;   // 0..7
    const int tj_ = tid & 15;   // 0..15

    float sc_p = 0.f, c1_p = 0.f, sq_p = 0.f, q1_p = 0.f;
    float acc[4][4];
#pragma unroll
    for (int a = 0; a < 4; a++)
#pragma unroll
        for (int e = 0; e < 4; e++) acc[a][e] = 0.f;

    const float4* ctx4 = (const float4*)(ctx + ((size_t)b * LC + i0) * DD);
    const float4* q4   = (const float4*)(qst + (size_t)b * LQ * DD);

#pragma unroll 1
    for (int c = 0; c < 4; c++) {       // D chunks of 64
        __syncthreads();
        // --- load ctx chunk (premultiply by w_p; fuse sc / ctx1 dots) ---
#pragma unroll
        for (int k = 0; k < 4; k++) {
            int f  = cf0 + k * 4;       // float4 slot 0..15
            int dl = f * 4;
            int dg = c * 64 + dl;
            float4 v   = ctx4[(size_t)cr * (DD / 4) + c * 16 + f];
            float4 wcv = *(const float4*)(wc   + dg);
            float4 wiv = *(const float4*)(w_in + dg);
            float4 wpv = *(const float4*)(wp   + dg);
            sc_p += v.x * wcv.x + v.y * wcv.y + v.z * wcv.z + v.w * wcv.w;
            c1_p += v.x * wiv.x + v.y * wiv.y + v.z * wiv.z + v.w * wiv.w;
            float4 pv = make_float4(v.x * wpv.x, v.y * wpv.y, v.z * wpv.z, v.w * wpv.w);
            *(float4*)&sC[cr][dl] = pv;
        }
        // --- load q chunk (raw; fuse sq / q1 dots) ---
#pragma unroll
        for (int k = 0; k < 8; k++) {
            int f  = qf0 + k * 2;
            int dl = f * 4;
            int dg = c * 64 + dl;
            float4 v   = q4[(size_t)qr * (DD / 4) + c * 16 + f];
            float4 wqv = *(const float4*)(wq    + dg);
            float4 wmv = *(const float4*)(w_mem + dg);
            sq_p += v.x * wqv.x + v.y * wqv.y + v.z * wqv.z + v.w * wqv.w;
            q1_p += v.x * wmv.x + v.y * wmv.y + v.z * wmv.z + v.w * wmv.w;
            *(float4*)&sQ[qr][dl] = v;
        }
        __syncthreads();
        // --- register-tiled GEMM over this chunk ---
#pragma unroll 4
        for (int d = 0; d < 64; d += 4) {
            float4 cv[4], qv[4];
#pragma unroll
            for (int a = 0; a < 4; a++) cv[a] = *(const float4*)&sC[ti_ * 4 + a][d];
#pragma unroll
            for (int a = 0; a < 4; a++) qv[a] = *(const float4*)&sQ[tj_ * 4 + a][d];
#pragma unroll
            for (int a = 0; a < 4; a++)
#pragma unroll
                for (int e = 0; e < 4; e++) {
                    acc[a][e] += cv[a].x * qv[e].x;
                    acc[a][e] += cv[a].y * qv[e].y;
                    acc[a][e] += cv[a].z * qv[e].z;
                    acc[a][e] += cv[a].w * qv[e].w;
                }
        }
    }

    // --- reduce fused row-dot partials (groups are warp-contiguous) ---
    sc_p += __shfl_xor_sync(0xffffffffu, sc_p, 1);
    sc_p += __shfl_xor_sync(0xffffffffu, sc_p, 2);
    c1_p += __shfl_xor_sync(0xffffffffu, c1_p, 1);
    c1_p += __shfl_xor_sync(0xffffffffu, c1_p, 2);
    if ((tid & 3) == 0) { s_sc[cr] = sc_p; s_c1[cr] = c1_p; }
    sq_p += __shfl_xor_sync(0xffffffffu, sq_p, 1);
    q1_p += __shfl_xor_sync(0xffffffffu, q1_p, 1);
    if ((tid & 1) == 0) { s_sq[qr] = sq_p; s_q1[qr] = q1_p; }
    __syncthreads();

    const float bias = att_b[0];

    // per-thread j-column constants
    float myq1[4], addj[4];
#pragma unroll
    for (int e = 0; e < 4; e++) {
        int j = tj_ * 4 + e;
        myq1[e] = s_q1[j];
        addj[e] = s_sq[j] + s_pen[j] + bias;
    }

    // --- softmax over j, fully in registers + 16-lane shuffles ---
#pragma unroll
    for (int a = 0; a < 4; a++) {
        int i = ti_ * 4 + a;
        float sci = s_sc[i];
        float l[4];
        float mx = -INFINITY;
#pragma unroll
        for (int e = 0; e < 4; e++) {
            l[e] = acc[a][e] + sci + addj[e];
            mx = fmaxf(mx, l[e]);
        }
#pragma unroll
        for (int s = 1; s < 16; s <<= 1)
            mx = fmaxf(mx, __shfl_xor_sync(0xffffffffu, mx, s));
        float num = 0.f, den = 0.f;
#pragma unroll
        for (int e = 0; e < 4; e++) {
            float ev = __expf(l[e] - mx);
            num += ev * myq1[e];
            den += ev;
        }
#pragma unroll
        for (int s = 1; s < 16; s <<= 1) {
            num += __shfl_xor_sync(0xffffffffu, num, s);
            den += __shfl_xor_sync(0xffffffffu, den, s);
        }
        if (tj_ == 0) {
            int gi = b * LC + i0 + i;
            g_U[gi]    = num / den;
            g_m[gi]    = mx;
            g_ctx1[gi] = s_c1[i];
        }
    }
}

__global__ __launch_bounds__(256) void bi_attn_final(float* __restrict__ out)
{
    __shared__ float red[256];
    const int b   = blockIdx.x;
    const int tid = threadIdx.x;

    float m0 = g_m[b * LC + tid];
    float m1 = g_m[b * LC + tid + 256];
    float c10 = g_ctx1[b * LC + tid];
    float c11 = g_ctx1[b * LC + tid + 256];

    // block max over 512 rowmaxes
    red[tid] = fmaxf(m0, m1);
    __syncthreads();
    for (int s = 128; s > 0; s >>= 1) {
        if (tid < s) red[tid] = fmaxf(red[tid], red[tid + s]);
        __syncthreads();
    }
    float M = red[0];
    __syncthreads();

    float e0 = __expf(m0 - M), e1 = __expf(m1 - M);
    float den = e0 + e1;
    float num = e0 * c10 + e1 * c11;

    red[tid] = den;
    __syncthreads();
    for (int s = 128; s > 0; s >>= 1) {
        if (tid < s) red[tid] += red[tid + s];
        __syncthreads();
    }
    float DEN = red[0];
    __syncthreads();

    red[tid] = num;
    __syncthreads();
    for (int s = 128; s > 0; s >>= 1) {
        if (tid < s) red[tid] += red[tid + s];
        __syncthreads();
    }
    float H = red[0] / DEN;
    __syncthreads();

    // write G = [ctx1, U, ctx1*U, U*H]
#pragma unroll
    for (int r = 0; r < 2; r++) {
        int i = tid + r * 256;
        float c1 = r ? c11 : c10;
        float u  = g_U[b * LC + i];
        float4 o = make_float4(c1, u, c1 * u, u * H);
        ((float4*)out)[(size_t)b * LC + i] = o;
    }
}

extern "C" void kernel_launch(void* const* d_in, const int* in_sizes, int n_in,
                              void* d_out, int out_size)
{
    const float* ctx   = (const float*)d_in[0];  // (8,512,256)
    const float* qst   = (const float*)d_in[1];  // (8,64,256)
    const int*   mask  = (const int*)d_in[2];    // (8,64)
    const float* att_w = (const float*)d_in[3];  // (768,)
    const float* att_b = (const float*)d_in[4];  // (1,)
    const float* w_in  = (const float*)d_in[5];  // (256,)
    const float* w_mem = (const float*)d_in[6];  // (256,)
    float* out = (float*)d_out;                  // (8,512,4)

    dim3 grid(LC / TI, BB);
    bi_attn_main<<<grid, 128>>>(ctx, qst, mask, att_w, att_b, w_in, w_mem);
    bi_attn_final<<<BB, 256>>>(out);
}

// round 4
// speedup vs baseline: 1.4129x; 1.4129x over previous
#include <cuda_runtime.h>
#include <math.h>

#define BB 8
#define LC 512
#define LQ 64
#define DD 256
#define TI 32
#define W  32                 // D-chunk width
#define CH (DD / W)           // 8 chunks
#define SCS 36                // sC row stride (words), 16B-aligned
#define SQS 68                // sQT row stride (words), 16B-aligned
#define NEG_BIG 1e30f

__device__ float g_ctx1[BB * LC];
__device__ float g_U[BB * LC];
__device__ float g_m[BB * LC];
__device__ unsigned int g_cnt[BB];

__global__ __launch_bounds__(128) void bi_attn_fused(
    const float* __restrict__ ctx, const float* __restrict__ qst,
    const int* __restrict__ mask, const float* __restrict__ att_w,
    const float* __restrict__ att_b, const float* __restrict__ w_in,
    const float* __restrict__ w_mem, float* __restrict__ out)
{
    __shared__ __align__(16) float sC[2][TI][SCS];     // ctx rows * w_p (double buffered)
    __shared__ __align__(16) float sQT[2][W][SQS];     // question TRANSPOSED: [d][j]
    __shared__ __align__(16) float sw[5 * DD];         // wc | w_in | wp | wq | w_mem
    __shared__ float s_sc[TI], s_c1[TI], s_sq[LQ], s_q1[LQ], s_pen[LQ];
    __shared__ float s_red[8];
    __shared__ unsigned s_last;

    const int b   = blockIdx.y;
    const int i0  = blockIdx.x * TI;
    const int tid = threadIdx.x;

    // ---- one-time: weights -> smem ----
    // layout: [0,D)=wc  [D,2D)=w_in  [2D,3D)=wp  [3D,4D)=wq  [4D,5D)=w_mem
    for (int i = tid; i < 5 * DD; i += 128) {
        float v;
        if      (i < DD)      v = att_w[i];             // wc   = att_w[0..256)
        else if (i < 2 * DD)  v = w_in[i - DD];         // w_in
        else if (i < 3 * DD)  v = att_w[i];             // wp   = att_w[512..768)  (FIXED)
        else if (i < 4 * DD)  v = att_w[i - 2 * DD];    // wq   = att_w[256..512)
        else                  v = w_mem[i - 4 * DD];    // w_mem
        sw[i] = v;
    }
    if (tid < LQ) {
        float mf = (float)mask[b * LQ + tid];
        s_pen[tid] = -NEG_BIG * (1.0f - mf);
    }

    // load-thread mapping
    const int cr  = tid >> 2;   // ctx row 0..31 (4 thr/row)
    const int cf0 = tid & 3;
    const int qr  = tid >> 1;   // q row 0..63 (2 thr/row)
    const int qf0 = tid & 1;
    // GEMM mapping: 8 i-groups x 16 j-groups, 4x4 tile
    const int ti_ = tid >> 4;
    const int tj_ = tid & 15;

    float sc_p = 0.f, c1_p = 0.f, sq_p = 0.f, q1_p = 0.f;
    float acc[4][4];
#pragma unroll
    for (int a = 0; a < 4; a++)
#pragma unroll
        for (int e = 0; e < 4; e++) acc[a][e] = 0.f;

    const float4* ctx4 = (const float4*)(ctx + ((size_t)b * LC + i0) * DD);
    const float4* q4   = (const float4*)(qst + (size_t)b * LQ * DD);

    float4 cd[2], qd[4];

    // prologue: prefetch chunk 0
#pragma unroll
    for (int k = 0; k < 2; k++) cd[k] = __ldg(&ctx4[(size_t)cr * 64 + cf0 + 4 * k]);
#pragma unroll
    for (int k = 0; k < 4; k++) qd[k] = __ldg(&q4[(size_t)qr * 64 + qf0 + 2 * k]);
    __syncthreads();   // weights visible

    // process+store chunk 0 into buffer 0
    {
#pragma unroll
        for (int k = 0; k < 2; k++) {
            int dl = (cf0 + 4 * k) * 4, dg = dl;
            float4 v = cd[k];
            float4 wcv = *(const float4*)&sw[dg];
            float4 wiv = *(const float4*)&sw[DD + dg];
            float4 wpv = *(const float4*)&sw[2 * DD + dg];
            sc_p += v.x * wcv.x + v.y * wcv.y + v.z * wcv.z + v.w * wcv.w;
            c1_p += v.x * wiv.x + v.y * wiv.y + v.z * wiv.z + v.w * wiv.w;
            *(float4*)&sC[0][cr][dl] =
                make_float4(v.x * wpv.x, v.y * wpv.y, v.z * wpv.z, v.w * wpv.w);
        }
#pragma unroll
        for (int k = 0; k < 4; k++) {
            int dl = (qf0 + 2 * k) * 4, dg = dl;
            float4 v = qd[k];
            float4 wqv = *(const float4*)&sw[3 * DD + dg];
            float4 wmv = *(const float4*)&sw[4 * DD + dg];
            sq_p += v.x * wqv.x + v.y * wqv.y + v.z * wqv.z + v.w * wqv.w;
            q1_p += v.x * wmv.x + v.y * wmv.y + v.z * wmv.z + v.w * wmv.w;
            sQT[0][dl + 0][qr] = v.x;
            sQT[0][dl + 1][qr] = v.y;
            sQT[0][dl + 2][qr] = v.z;
            sQT[0][dl + 3][qr] = v.w;
        }
    }
    __syncthreads();

#pragma unroll 1
    for (int c = 0; c < CH; c++) {
        const int buf = c & 1;
        if (c + 1 < CH) {   // prefetch next chunk (LDG latency hidden by GEMM)
#pragma unroll
            for (int k = 0; k < 2; k++)
                cd[k] = __ldg(&ctx4[(size_t)cr * 64 + (c + 1) * 8 + cf0 + 4 * k]);
#pragma unroll
            for (int k = 0; k < 4; k++)
                qd[k] = __ldg(&q4[(size_t)qr * 64 + (c + 1) * 8 + qf0 + 2 * k]);
        }
        // GEMM on current buffer (conflict-free: qv reads are j-contiguous)
#pragma unroll
        for (int d = 0; d < W; d += 4) {
            float4 cv[4], qv[4];
#pragma unroll
            for (int a = 0; a < 4; a++) cv[a] = *(const float4*)&sC[buf][ti_ * 4 + a][d];
#pragma unroll
            for (int dd = 0; dd < 4; dd++) qv[dd] = *(const float4*)&sQT[buf][d + dd][tj_ * 4];
#pragma unroll
            for (int a = 0; a < 4; a++) {
                const float cx = cv[a].x, cy = cv[a].y, cz = cv[a].z, cw = cv[a].w;
#pragma unroll
                for (int e = 0; e < 4; e++) {
                    float q0 = ((const float*)&qv[0])[e];
                    float q1 = ((const float*)&qv[1])[e];
                    float q2 = ((const float*)&qv[2])[e];
                    float q3 = ((const float*)&qv[3])[e];
                    acc[a][e] += cx * q0 + cy * q1 + cz * q2 + cw * q3;
                }
            }
        }
        if (c + 1 < CH) {   // process + store next chunk into other buffer
            const int nb = buf ^ 1;
            const int cg = (c + 1) * W;
#pragma unroll
            for (int k = 0; k < 2; k++) {
                int dl = (cf0 + 4 * k) * 4, dg = cg + dl;
                float4 v = cd[k];
                float4 wcv = *(const float4*)&sw[dg];
                float4 wiv = *(const float4*)&sw[DD + dg];
                float4 wpv = *(const float4*)&sw[2 * DD + dg];
                sc_p += v.x * wcv.x + v.y * wcv.y + v.z * wcv.z + v.w * wcv.w;
                c1_p += v.x * wiv.x + v.y * wiv.y + v.z * wiv.z + v.w * wiv.w;
                *(float4*)&sC[nb][cr][dl] =
                    make_float4(v.x * wpv.x, v.y * wpv.y, v.z * wpv.z, v.w * wpv.w);
            }
#pragma unroll
            for (int k = 0; k < 4; k++) {
                int dl = (qf0 + 2 * k) * 4, dg = cg + dl;
                float4 v = qd[k];
                float4 wqv = *(const float4*)&sw[3 * DD + dg];
                float4 wmv = *(const float4*)&sw[4 * DD + dg];
                sq_p += v.x * wqv.x + v.y * wqv.y + v.z * wqv.z + v.w * wqv.w;
                q1_p += v.x * wmv.x + v.y * wmv.y + v.z * wmv.z + v.w * wmv.w;
                sQT[nb][dl + 0][qr] = v.x;
                sQT[nb][dl + 1][qr] = v.y;
                sQT[nb][dl + 2][qr] = v.z;
                sQT[nb][dl + 3][qr] = v.w;
            }
        }
        __syncthreads();
    }

    // ---- reduce fused row-dot partials ----
    sc_p += __shfl_xor_sync(0xffffffffu, sc_p, 1);
    sc_p += __shfl_xor_sync(0xffffffffu, sc_p, 2);
    c1_p += __shfl_xor_sync(0xffffffffu, c1_p, 1);
    c1_p += __shfl_xor_sync(0xffffffffu, c1_p, 2);
    if (cf0 == 0) { s_sc[cr] = sc_p; s_c1[cr] = c1_p; }
    sq_p += __shfl_xor_sync(0xffffffffu, sq_p, 1);
    q1_p += __shfl_xor_sync(0xffffffffu, q1_p, 1);
    if (qf0 == 0) { s_sq[qr] = sq_p; s_q1[qr] = q1_p; }
    __syncthreads();

    const float bias = att_b[0];
    float myq1[4], addj[4];
#pragma unroll
    for (int e = 0; e < 4; e++) {
        int j = tj_ * 4 + e;
        myq1[e] = s_q1[j];
        addj[e] = s_sq[j] + s_pen[j] + bias;
    }

    // ---- per-row softmax over j (registers + 16-lane shuffles) ----
#pragma unroll
    for (int a = 0; a < 4; a++) {
        int i = ti_ * 4 + a;
        float sci = s_sc[i];
        float l[4], mx = -INFINITY;
#pragma unroll
        for (int e = 0; e < 4; e++) {
            l[e] = acc[a][e] + sci + addj[e];
            mx = fmaxf(mx, l[e]);
        }
#pragma unroll
        for (int s = 1; s < 16; s <<= 1)
            mx = fmaxf(mx, __shfl_xor_sync(0xffffffffu, mx, s));
        float num = 0.f, den = 0.f;
#pragma unroll
        for (int e = 0; e < 4; e++) {
            float ev = __expf(l[e] - mx);
            num += ev * myq1[e];
            den += ev;
        }
#pragma unroll
        for (int s = 1; s < 16; s <<= 1) {
            num += __shfl_xor_sync(0xffffffffu, num, s);
            den += __shfl_xor_sync(0xffffffffu, den, s);
        }
        if (tj_ == 0) {
            int gi = b * LC + i0 + i;
            g_U[gi]    = num / den;
            g_m[gi]    = mx;
            g_ctx1[gi] = s_c1[i];
        }
    }

    // ---- fused finalization: last block of this batch does the 512-softmax ----
    __threadfence();
    __syncthreads();
    if (tid == 0) s_last = (atomicAdd(&g_cnt[b], 1u) == (LC / TI) - 1u) ? 1u : 0u;
    __syncthreads();
    if (!s_last) return;
    __threadfence();   // acquire: order following loads after the counter read

    const int wid = tid >> 5, lid = tid & 31;
    float m[4], c1[4];
#pragma unroll
    for (int k = 0; k < 4; k++) {
        int idx = tid + 128 * k;
        m[k]  = __ldcg(&g_m[b * LC + idx]);
        c1[k] = __ldcg(&g_ctx1[b * LC + idx]);
    }
    float mx = fmaxf(fmaxf(m[0], m[1]), fmaxf(m[2], m[3]));
#pragma unroll
    for (int s = 16; s > 0; s >>= 1)
        mx = fmaxf(mx, __shfl_xor_sync(0xffffffffu, mx, s));
    if (lid == 0) s_red[wid] = mx;
    __syncthreads();
    float M = fmaxf(fmaxf(s_red[0], s_red[1]), fmaxf(s_red[2], s_red[3]));
    __syncthreads();

    float den = 0.f, num = 0.f, ev[4];
#pragma unroll
    for (int k = 0; k < 4; k++) {
        ev[k] = __expf(m[k] - M);
        den += ev[k];
        num += ev[k] * c1[k];
    }
#pragma unroll
    for (int s = 16; s > 0; s >>= 1) {
        den += __shfl_xor_sync(0xffffffffu, den, s);
        num += __shfl_xor_sync(0xffffffffu, num, s);
    }
    if (lid == 0) { s_red[wid] = den; s_red[4 + wid] = num; }
    __syncthreads();
    float DEN = s_red[0] + s_red[1] + s_red[2] + s_red[3];
    float NUM = s_red[4] + s_red[5] + s_red[6] + s_red[7];
    float H = NUM / DEN;

#pragma unroll
    for (int k = 0; k < 4; k++) {
        int idx = tid + 128 * k;
        float u = __ldcg(&g_U[b * LC + idx]);
        ((float4*)out)[(size_t)b * LC + idx] = make_float4(c1[k], u, c1[k] * u, u * H);
    }
    if (tid == 0) g_cnt[b] = 0;   // reset for next graph replay
}

extern "C" void kernel_launch(void* const* d_in, const int* in_sizes, int n_in,
                              void* d_out, int out_size)
{
    const float* ctx   = (const float*)d_in[0];  // (8,512,256)
    const float* qst   = (const float*)d_in[1];  // (8,64,256)
    const int*   mask  = (const int*)d_in[2];    // (8,64)
    const float* att_w = (const float*)d_in[3];  // (768,)
    const float* att_b = (const float*)d_in[4];  // (1,)
    const float* w_in  = (const float*)d_in[5];  // (256,)
    const float* w_mem = (const float*)d_in[6];  // (256,)
    float* out = (float*)d_out;                  // (8,512,4)

    dim3 grid(LC / TI, BB);
    bi_attn_fused<<<grid, 128>>>(ctx, qst, mask, att_w, att_b, w_in, w_mem, out);
}